// round 5
// baseline (speedup 1.0000x reference)
#include <cuda_runtime.h>
#include <cuda_bf16.h>
#include <cstdint>

// Problem constants (fixed by reference: N=8192, D=256, K=8)
#define NC 1024      // number of classes
#define DD 256       // feature dim
#define KPC 8        // samples per class
#define NTOT (NC*KPC)

__device__ __forceinline__ uint32_t smem_to_u32(const void* smem_ptr) {
    uint32_t addr;
    asm("{ .reg .u64 tmp; cvta.to.shared.u64 tmp, %1; cvt.u32.u64 %0, tmp; }"
        : "=r"(addr) : "l"(smem_ptr));
    return addr;
}

// ---------------------------------------------------------------------------
// Scratch (device globals; no allocation allowed)
// ---------------------------------------------------------------------------
__device__ __nv_bfloat16 g_centers_bf[NC * DD];  // bf16 class centers (MMA input)
__device__ float  g_sq[NC];                      // ||center||^2 per class (fp32)
__device__ float  g_distpc[NC];                  // sum of 8 dist_pc values per class
__device__ float  g_blocksum[256];               // per-gram-block hinge totals
__device__ unsigned int g_count = 0;             // completion counter (self-resetting)

// ---------------------------------------------------------------------------
// Kernel A: warp-per-class, 64-thread blocks (2 classes/block) for occupancy.
// ---------------------------------------------------------------------------
__global__ void __launch_bounds__(64) class_kernel(const float* __restrict__ x)
{
    const int wid  = threadIdx.x >> 5;
    const int lane = threadIdx.x & 31;
    const int c    = blockIdx.x * 2 + wid;

    const float* base = x + (size_t)(c * KPC) * DD + lane * 8;

    float v[KPC][8];
#pragma unroll
    for (int r = 0; r < KPC; r++) {
        float4 a = *(const float4*)(base + r * DD);
        float4 b = *(const float4*)(base + r * DD + 4);
        v[r][0] = a.x; v[r][1] = a.y; v[r][2] = a.z; v[r][3] = a.w;
        v[r][4] = b.x; v[r][5] = b.y; v[r][6] = b.z; v[r][7] = b.w;
    }

    float s[KPC];
#pragma unroll
    for (int r = 0; r < KPC; r++) {
        float t = 0.f;
#pragma unroll
        for (int j = 0; j < 8; j++) t += v[r][j] * v[r][j];
        s[r] = t;
    }
#pragma unroll
    for (int off = 16; off; off >>= 1)
#pragma unroll
        for (int r = 0; r < KPC; r++)
            s[r] += __shfl_xor_sync(0xffffffffu, s[r], off);

    float ctr[8];
#pragma unroll
    for (int j = 0; j < 8; j++) ctr[j] = 0.f;
#pragma unroll
    for (int r = 0; r < KPC; r++) {
        float inv = rsqrtf(s[r]);
#pragma unroll
        for (int j = 0; j < 8; j++) { v[r][j] *= inv; ctr[j] += v[r][j]; }
    }
#pragma unroll
    for (int j = 0; j < 8; j++) ctr[j] *= (1.0f / KPC);

    {
        __nv_bfloat162 p0 = __floats2bfloat162_rn(ctr[0], ctr[1]);
        __nv_bfloat162 p1 = __floats2bfloat162_rn(ctr[2], ctr[3]);
        __nv_bfloat162 p2 = __floats2bfloat162_rn(ctr[4], ctr[5]);
        __nv_bfloat162 p3 = __floats2bfloat162_rn(ctr[6], ctr[7]);
        uint4 u;
        u.x = *(uint32_t*)&p0; u.y = *(uint32_t*)&p1;
        u.z = *(uint32_t*)&p2; u.w = *(uint32_t*)&p3;
        *(uint4*)(&g_centers_bf[c * DD + lane * 8]) = u;
    }

    float cs = 0.f;
#pragma unroll
    for (int j = 0; j < 8; j++) cs += ctr[j] * ctr[j];
#pragma unroll
    for (int off = 16; off; off >>= 1)
        cs += __shfl_xor_sync(0xffffffffu, cs, off);
    if (lane == 0) g_sq[c] = cs;

    const float bc = rsqrtf(cs);
    float cn[8];
#pragma unroll
    for (int j = 0; j < 8; j++) cn[j] = ctr[j] * bc;

    float dd2[KPC];
#pragma unroll
    for (int r = 0; r < KPC; r++) {
        float t = 0.f;
#pragma unroll
        for (int j = 0; j < 8; j++) { float e = v[r][j] - cn[j]; t += e * e; }
        dd2[r] = t;
    }
#pragma unroll
    for (int off = 16; off; off >>= 1)
#pragma unroll
        for (int r = 0; r < KPC; r++)
            dd2[r] += __shfl_xor_sync(0xffffffffu, dd2[r], off);

    if (lane == 0) {
        float acc = 0.f;
#pragma unroll
        for (int r = 0; r < KPC; r++) acc += sqrtf(dd2[r]);  // MARGIN1 = 0
        g_distpc[c] = acc;
    }
}

// ---------------------------------------------------------------------------
// Kernel B: bf16 mma.sync Gram, 64x64 tiles, cp.async 2-stage K pipeline,
// fused hinge + fused final reduction. grid 16x16 = 256 blocks, 256 threads,
// 2 blocks/SM. 8 warps = 4(row strips of 16) x 2(col strips of 32).
// ---------------------------------------------------------------------------
#define ROWB 528                     // padded row stride in bytes (264 bf16)
#define SMEM_SQR 0                   // 64 floats (row sq)
#define SMEM_SQC 256                 // 64 floats (col sq)
#define SMEM_A   1024                // 64 rows * 528 B = 33792
#define SMEM_B   (1024 + 33792)      // 64 rows * 528 B = 33792
#define GRAM_SMEM (SMEM_B + 33792)   // 68608 B

#define CP_ASYNC_16(dst, src) \
    asm volatile("cp.async.cg.shared.global [%0], [%1], 16;" :: "r"(dst), "l"(src))
#define CP_COMMIT() asm volatile("cp.async.commit_group;" ::: "memory")
#define CP_WAIT(n)  asm volatile("cp.async.wait_group %0;" :: "n"(n) : "memory")

__device__ __forceinline__ void ldsm_x4(uint32_t* r, uint32_t addr) {
    asm volatile("ldmatrix.sync.aligned.m8n8.x4.shared.b16 {%0,%1,%2,%3}, [%4];"
        : "=r"(r[0]), "=r"(r[1]), "=r"(r[2]), "=r"(r[3]) : "r"(addr));
}
__device__ __forceinline__ void mma_bf16(float* c, const uint32_t* a, const uint32_t* b) {
    asm volatile(
        "mma.sync.aligned.m16n8k16.row.col.f32.bf16.bf16.f32 "
        "{%0,%1,%2,%3}, {%4,%5,%6,%7}, {%8,%9}, {%0,%1,%2,%3};"
        : "+f"(c[0]), "+f"(c[1]), "+f"(c[2]), "+f"(c[3])
        : "r"(a[0]), "r"(a[1]), "r"(a[2]), "r"(a[3]), "r"(b[0]), "r"(b[1]));
}

__global__ void __launch_bounds__(256, 2) gram_kernel(float* __restrict__ out, int n_out)
{
    extern __shared__ char smem[];
    const uint32_t sbase = smem_to_u32(smem);
    const int tid  = threadIdx.x;
    const int warp = tid >> 5;
    const int lane = tid & 31;
    const int wrow = warp & 3;       // 0..3 -> 16-row strip
    const int wcol = warp >> 2;      // 0..1 -> 32-col strip
    const int rb   = blockIdx.y * 64;
    const int cb   = blockIdx.x * 64;

    // ---- cp.async staging: two K-half stages (chunks 0..15, 16..31 per row)
    // rows 0..63 = A tile, rows 64..127 = B tile; 16B chunks.
#pragma unroll
    for (int s = 0; s < 2; s++) {
#pragma unroll
        for (int it = 0; it < 8; it++) {
            int ch  = tid + it * 256;          // 0..2047
            int row = ch >> 4;                 // 0..127
            int cq  = (ch & 15) + s * 16;      // chunk 0..31
            int gr  = (row < 64) ? (rb + row) : (cb + row - 64);
            uint32_t dst = sbase + ((row < 64) ? SMEM_A + row * ROWB
                                               : SMEM_B + (row - 64) * ROWB) + cq * 16;
            CP_ASYNC_16(dst, (const char*)&g_centers_bf[gr * DD + cq * 8]);
        }
        CP_COMMIT();
    }

    // stage sq values (regular loads, independent of cp.async)
    if (tid < 64)        ((float*)(smem + SMEM_SQR))[tid]      = g_sq[rb + tid];
    else if (tid < 128)  ((float*)(smem + SMEM_SQC))[tid - 64] = g_sq[cb + tid - 64];

    float acc[4][4];
#pragma unroll
    for (int ni = 0; ni < 4; ni++)
#pragma unroll
        for (int q = 0; q < 4; q++) acc[ni][q] = 0.f;

    // ldsm base addresses
    // A (16 rows x k16 via x4): lanes 0..15 -> rows, lanes 16..31 -> +16B chunk
    const uint32_t aBase = sbase + SMEM_A + (wrow * 16 + (lane & 15)) * ROWB + (lane >> 4) * 16;
    // B (n16 x k16 via x4): lanes {0-7,16-23} -> n rows {0-7,8-15}; lanes>>3 odd -> +16B
    const uint32_t bBase = sbase + SMEM_B
        + (wcol * 32 + (lane & 7) + ((lane >> 4) << 3)) * ROWB + ((lane >> 3) & 1) * 16;

    CP_WAIT(1);          // K-half 0 resident
    __syncthreads();

#pragma unroll
    for (int half = 0; half < 2; half++) {
        if (half == 1) { CP_WAIT(0); __syncthreads(); }
#pragma unroll
        for (int s0 = 0; s0 < 8; s0++) {
            const int koff = (half * 8 + s0) * 32;   // 32B per k16 step
            uint32_t a[4], b[2][4];
            ldsm_x4(a, aBase + koff);
            ldsm_x4(b[0], bBase + koff);
            ldsm_x4(b[1], bBase + 16 * ROWB + koff);
#pragma unroll
            for (int ni = 0; ni < 4; ni++)
                mma_bf16(acc[ni], a, &b[ni >> 1][(ni & 1) * 2]);
        }
    }

    // ---- fused hinge epilogue: single scalar per thread (loss is linear in it)
    const float* sqR = (const float*)(smem + SMEM_SQR);
    const float* sqC = (const float*)(smem + SMEM_SQC);
    float hsum = 0.f;
    {
        const int lr0 = wrow * 16 + (lane >> 2);
        const int lr1 = lr0 + 8;
        const float sq0 = sqR[lr0], sq1 = sqR[lr1];
        const int r0 = rb + lr0, r1 = rb + lr1;
#pragma unroll
        for (int ni = 0; ni < 4; ni++) {
#pragma unroll
            for (int q = 0; q < 2; q++) {
                const int lc  = wcol * 32 + ni * 8 + (lane & 3) * 2 + q;
                const int col = cb + lc;
                const float sqc = sqC[lc];
                if (col != r0) {
                    float dsq = sq0 + sqc - 2.0f * acc[ni][q];
                    hsum += fmaxf(0.7f - sqrtf(fmaxf(dsq, 1e-12f)), 0.f);
                }
                if (col != r1) {
                    float dsq = sq1 + sqc - 2.0f * acc[ni][q + 2];
                    hsum += fmaxf(0.7f - sqrtf(fmaxf(dsq, 1e-12f)), 0.f);
                }
            }
        }
    }
    // block reduction (fixed order -> deterministic)
#pragma unroll
    for (int off = 16; off; off >>= 1)
        hsum += __shfl_xor_sync(0xffffffffu, hsum, off);
    __shared__ float wsum[8];
    __shared__ int is_last;
    if (lane == 0) wsum[warp] = hsum;
    __syncthreads();

    const int bid = blockIdx.y * gridDim.x + blockIdx.x;   // 0..255
    if (tid == 0) {
        float bsum = 0.f;
#pragma unroll
        for (int w = 0; w < 8; w++) bsum += wsum[w];
        g_blocksum[bid] = bsum;
        __threadfence();
        unsigned int old = atomicAdd(&g_count, 1u);
        is_last = (old == 255u);
    }
    __syncthreads();

    // ---- last block: deterministic final reduction + output
    if (is_last) {
        float an = g_blocksum[tid];                         // 256 block partials
        float pc = 0.f;
#pragma unroll
        for (int p = 0; p < 4; p++) pc += g_distpc[tid + p * 256];
#pragma unroll
        for (int off = 16; off; off >>= 1) {
            an += __shfl_xor_sync(0xffffffffu, an, off);
            pc += __shfl_xor_sync(0xffffffffu, pc, off);
        }
        __shared__ float sa[8], sp[8];
        if (lane == 0) { sa[warp] = an; sp[warp] = pc; }
        __syncthreads();
        if (tid == 0) {
            float An = 0.f, Pc = 0.f;
#pragma unroll
            for (int w = 0; w < 8; w++) { An += sa[w]; Pc += sp[w]; }
            float anm = An * (1.0f / (1023.0f * NC));
            float pcm = Pc * (1.0f / NTOT);
            if (n_out > 0) out[0] = pcm + anm;
            if (n_out > 1) out[1] = pcm;
            if (n_out > 2) out[2] = anm;
            g_count = 0;   // self-reset for next graph replay
        }
    }
}

extern "C" void kernel_launch(void* const* d_in, const int* in_sizes, int n_in,
                              void* d_out, int out_size)
{
    const float* x = (const float*)d_in[0];
    (void)in_sizes; (void)n_in;

    cudaFuncSetAttribute(gram_kernel,
                         cudaFuncAttributeMaxDynamicSharedMemorySize, GRAM_SMEM);

    class_kernel<<<NC / 2, 64>>>(x);
    gram_kernel<<<dim3(16, 16), 256, GRAM_SMEM>>>((float*)d_out, out_size);
}

// round 6
// speedup vs baseline: 1.0151x; 1.0151x over previous
#include <cuda_runtime.h>
#include <cuda_bf16.h>
#include <cstdint>

// Problem constants (fixed by reference: N=8192, D=256, K=8)
#define NC 1024      // number of classes
#define DD 256       // feature dim
#define KPC 8        // samples per class
#define NTOT (NC*KPC)

__device__ __forceinline__ uint32_t smem_to_u32(const void* smem_ptr) {
    uint32_t addr;
    asm("{ .reg .u64 tmp; cvta.to.shared.u64 tmp, %1; cvt.u32.u64 %0, tmp; }"
        : "=r"(addr) : "l"(smem_ptr));
    return addr;
}

// ---------------------------------------------------------------------------
// Scratch (device globals; no allocation allowed)
// ---------------------------------------------------------------------------
__device__ __nv_bfloat16 g_centers_bf[NC * DD];  // bf16 class centers (MMA input)
__device__ float  g_sq[NC];                      // ||center||^2 per class (fp32)
__device__ float  g_distpc[NC];                  // sum of 8 dist_pc values per class
__device__ float  g_blocksum[256];               // per-gram-block hinge totals

// ---------------------------------------------------------------------------
// Kernel A: warp-per-class, 64-thread blocks (2 classes/block) for occupancy.
// ---------------------------------------------------------------------------
__global__ void __launch_bounds__(64) class_kernel(const float* __restrict__ x)
{
    const int wid  = threadIdx.x >> 5;
    const int lane = threadIdx.x & 31;
    const int c    = blockIdx.x * 2 + wid;

    const float* base = x + (size_t)(c * KPC) * DD + lane * 8;

    float v[KPC][8];
#pragma unroll
    for (int r = 0; r < KPC; r++) {
        float4 a = *(const float4*)(base + r * DD);
        float4 b = *(const float4*)(base + r * DD + 4);
        v[r][0] = a.x; v[r][1] = a.y; v[r][2] = a.z; v[r][3] = a.w;
        v[r][4] = b.x; v[r][5] = b.y; v[r][6] = b.z; v[r][7] = b.w;
    }

    float s[KPC];
#pragma unroll
    for (int r = 0; r < KPC; r++) {
        float t = 0.f;
#pragma unroll
        for (int j = 0; j < 8; j++) t += v[r][j] * v[r][j];
        s[r] = t;
    }
#pragma unroll
    for (int off = 16; off; off >>= 1)
#pragma unroll
        for (int r = 0; r < KPC; r++)
            s[r] += __shfl_xor_sync(0xffffffffu, s[r], off);

    float ctr[8];
#pragma unroll
    for (int j = 0; j < 8; j++) ctr[j] = 0.f;
#pragma unroll
    for (int r = 0; r < KPC; r++) {
        float inv = rsqrtf(s[r]);
#pragma unroll
        for (int j = 0; j < 8; j++) { v[r][j] *= inv; ctr[j] += v[r][j]; }
    }
#pragma unroll
    for (int j = 0; j < 8; j++) ctr[j] *= (1.0f / KPC);

    {
        __nv_bfloat162 p0 = __floats2bfloat162_rn(ctr[0], ctr[1]);
        __nv_bfloat162 p1 = __floats2bfloat162_rn(ctr[2], ctr[3]);
        __nv_bfloat162 p2 = __floats2bfloat162_rn(ctr[4], ctr[5]);
        __nv_bfloat162 p3 = __floats2bfloat162_rn(ctr[6], ctr[7]);
        uint4 u;
        u.x = *(uint32_t*)&p0; u.y = *(uint32_t*)&p1;
        u.z = *(uint32_t*)&p2; u.w = *(uint32_t*)&p3;
        *(uint4*)(&g_centers_bf[c * DD + lane * 8]) = u;
    }

    float cs = 0.f;
#pragma unroll
    for (int j = 0; j < 8; j++) cs += ctr[j] * ctr[j];
#pragma unroll
    for (int off = 16; off; off >>= 1)
        cs += __shfl_xor_sync(0xffffffffu, cs, off);
    if (lane == 0) g_sq[c] = cs;

    const float bc = rsqrtf(cs);
    float cn[8];
#pragma unroll
    for (int j = 0; j < 8; j++) cn[j] = ctr[j] * bc;

    float dd2[KPC];
#pragma unroll
    for (int r = 0; r < KPC; r++) {
        float t = 0.f;
#pragma unroll
        for (int j = 0; j < 8; j++) { float e = v[r][j] - cn[j]; t += e * e; }
        dd2[r] = t;
    }
#pragma unroll
    for (int off = 16; off; off >>= 1)
#pragma unroll
        for (int r = 0; r < KPC; r++)
            dd2[r] += __shfl_xor_sync(0xffffffffu, dd2[r], off);

    if (lane == 0) {
        float acc = 0.f;
#pragma unroll
        for (int r = 0; r < KPC; r++) acc += sqrtf(dd2[r]);  // MARGIN1 = 0
        g_distpc[c] = acc;
    }
}

// ---------------------------------------------------------------------------
// Kernel B: bf16 mma.sync Gram, 64x64 tiles, cp.async 2-stage K pipeline,
// fused hinge -> ONE float per block (no fence, no atomic).
// grid 16x16 = 256 blocks, 256 threads, 2 blocks/SM.
// ---------------------------------------------------------------------------
#define ROWB 528                     // padded row stride in bytes (264 bf16)
#define SMEM_SQR 0                   // 64 floats (row sq)
#define SMEM_SQC 256                 // 64 floats (col sq)
#define SMEM_A   1024                // 64 rows * 528 B = 33792
#define SMEM_B   (1024 + 33792)      // 64 rows * 528 B = 33792
#define GRAM_SMEM (SMEM_B + 33792)   // 68608 B

#define CP_ASYNC_16(dst, src) \
    asm volatile("cp.async.cg.shared.global [%0], [%1], 16;" :: "r"(dst), "l"(src))
#define CP_COMMIT() asm volatile("cp.async.commit_group;" ::: "memory")
#define CP_WAIT(n)  asm volatile("cp.async.wait_group %0;" :: "n"(n) : "memory")

__device__ __forceinline__ void ldsm_x4(uint32_t* r, uint32_t addr) {
    asm volatile("ldmatrix.sync.aligned.m8n8.x4.shared.b16 {%0,%1,%2,%3}, [%4];"
        : "=r"(r[0]), "=r"(r[1]), "=r"(r[2]), "=r"(r[3]) : "r"(addr));
}
__device__ __forceinline__ void mma_bf16(float* c, const uint32_t* a, const uint32_t* b) {
    asm volatile(
        "mma.sync.aligned.m16n8k16.row.col.f32.bf16.bf16.f32 "
        "{%0,%1,%2,%3}, {%4,%5,%6,%7}, {%8,%9}, {%0,%1,%2,%3};"
        : "+f"(c[0]), "+f"(c[1]), "+f"(c[2]), "+f"(c[3])
        : "r"(a[0]), "r"(a[1]), "r"(a[2]), "r"(a[3]), "r"(b[0]), "r"(b[1]));
}

__global__ void __launch_bounds__(256, 2) gram_kernel()
{
    extern __shared__ char smem[];
    const uint32_t sbase = smem_to_u32(smem);
    const int tid  = threadIdx.x;
    const int warp = tid >> 5;
    const int lane = tid & 31;
    const int wrow = warp & 3;       // 0..3 -> 16-row strip
    const int wcol = warp >> 2;      // 0..1 -> 32-col strip
    const int rb   = blockIdx.y * 64;
    const int cb   = blockIdx.x * 64;

    // ---- cp.async staging: two K-half stages (chunks 0..15, 16..31 per row)
#pragma unroll
    for (int s = 0; s < 2; s++) {
#pragma unroll
        for (int it = 0; it < 8; it++) {
            int ch  = tid + it * 256;          // 0..2047
            int row = ch >> 4;                 // 0..127
            int cq  = (ch & 15) + s * 16;      // chunk 0..31
            int gr  = (row < 64) ? (rb + row) : (cb + row - 64);
            uint32_t dst = sbase + ((row < 64) ? SMEM_A + row * ROWB
                                               : SMEM_B + (row - 64) * ROWB) + cq * 16;
            CP_ASYNC_16(dst, (const char*)&g_centers_bf[gr * DD + cq * 8]);
        }
        CP_COMMIT();
    }

    // stage sq values (regular loads, independent of cp.async)
    if (tid < 64)        ((float*)(smem + SMEM_SQR))[tid]      = g_sq[rb + tid];
    else if (tid < 128)  ((float*)(smem + SMEM_SQC))[tid - 64] = g_sq[cb + tid - 64];

    float acc[4][4];
#pragma unroll
    for (int ni = 0; ni < 4; ni++)
#pragma unroll
        for (int q = 0; q < 4; q++) acc[ni][q] = 0.f;

    const uint32_t aBase = sbase + SMEM_A + (wrow * 16 + (lane & 15)) * ROWB + (lane >> 4) * 16;
    const uint32_t bBase = sbase + SMEM_B
        + (wcol * 32 + (lane & 7) + ((lane >> 4) << 3)) * ROWB + ((lane >> 3) & 1) * 16;

    CP_WAIT(1);          // K-half 0 resident
    __syncthreads();

#pragma unroll
    for (int half = 0; half < 2; half++) {
        if (half == 1) { CP_WAIT(0); __syncthreads(); }
#pragma unroll
        for (int s0 = 0; s0 < 8; s0++) {
            const int koff = (half * 8 + s0) * 32;   // 32B per k16 step
            uint32_t a[4], b[2][4];
            ldsm_x4(a, aBase + koff);
            ldsm_x4(b[0], bBase + koff);
            ldsm_x4(b[1], bBase + 16 * ROWB + koff);
#pragma unroll
            for (int ni = 0; ni < 4; ni++)
                mma_bf16(acc[ni], a, &b[ni >> 1][(ni & 1) * 2]);
        }
    }

    // ---- fused hinge epilogue: single scalar per thread (loss is linear in it)
    const float* sqR = (const float*)(smem + SMEM_SQR);
    const float* sqC = (const float*)(smem + SMEM_SQC);
    float hsum = 0.f;
    {
        const int lr0 = wrow * 16 + (lane >> 2);
        const int lr1 = lr0 + 8;
        const float sq0 = sqR[lr0], sq1 = sqR[lr1];
        const int r0 = rb + lr0, r1 = rb + lr1;
#pragma unroll
        for (int ni = 0; ni < 4; ni++) {
#pragma unroll
            for (int q = 0; q < 2; q++) {
                const int lc  = wcol * 32 + ni * 8 + (lane & 3) * 2 + q;
                const int col = cb + lc;
                const float sqc = sqC[lc];
                if (col != r0) {
                    float dsq = sq0 + sqc - 2.0f * acc[ni][q];
                    hsum += fmaxf(0.7f - sqrtf(fmaxf(dsq, 1e-12f)), 0.f);
                }
                if (col != r1) {
                    float dsq = sq1 + sqc - 2.0f * acc[ni][q + 2];
                    hsum += fmaxf(0.7f - sqrtf(fmaxf(dsq, 1e-12f)), 0.f);
                }
            }
        }
    }
    // block reduction (fixed order -> deterministic), then one plain store
#pragma unroll
    for (int off = 16; off; off >>= 1)
        hsum += __shfl_xor_sync(0xffffffffu, hsum, off);
    __shared__ float wsum[8];
    if (lane == 0) wsum[warp] = hsum;
    __syncthreads();
    if (tid == 0) {
        float bsum = 0.f;
#pragma unroll
        for (int w = 0; w < 8; w++) bsum += wsum[w];
        g_blocksum[blockIdx.y * gridDim.x + blockIdx.x] = bsum;
    }
}

// ---------------------------------------------------------------------------
// Kernel C: final reduction -> (loss, dist_pc_mean, dist_an_mean)
// ---------------------------------------------------------------------------
__global__ void __launch_bounds__(256) final_kernel(float* __restrict__ out, int n_out)
{
    const int t    = threadIdx.x;
    const int lane = t & 31;
    const int warp = t >> 5;

    float an = g_blocksum[t];        // 256 block partials
    float pc = 0.f;
#pragma unroll
    for (int p = 0; p < 4; p++) pc += g_distpc[t + p * 256];

#pragma unroll
    for (int off = 16; off; off >>= 1) {
        an += __shfl_xor_sync(0xffffffffu, an, off);
        pc += __shfl_xor_sync(0xffffffffu, pc, off);
    }
    __shared__ float sa[8], sp[8];
    if (lane == 0) { sa[warp] = an; sp[warp] = pc; }
    __syncthreads();
    if (t == 0) {
        float An = 0.f, Pc = 0.f;
#pragma unroll
        for (int w = 0; w < 8; w++) { An += sa[w]; Pc += sp[w]; }
        float anm = An * (1.0f / (1023.0f * NC));
        float pcm = Pc * (1.0f / NTOT);
        if (n_out > 0) out[0] = pcm + anm;
        if (n_out > 1) out[1] = pcm;
        if (n_out > 2) out[2] = anm;
    }
}

extern "C" void kernel_launch(void* const* d_in, const int* in_sizes, int n_in,
                              void* d_out, int out_size)
{
    const float* x = (const float*)d_in[0];
    (void)in_sizes; (void)n_in;

    cudaFuncSetAttribute(gram_kernel,
                         cudaFuncAttributeMaxDynamicSharedMemorySize, GRAM_SMEM);

    class_kernel<<<NC / 2, 64>>>(x);
    gram_kernel<<<dim3(16, 16), 256, GRAM_SMEM>>>();
    final_kernel<<<1, 256>>>((float*)d_out, out_size);
}